// round 17
// baseline (speedup 1.0000x reference)
#include <cuda_runtime.h>
#include <cuda_fp16.h>
#include <math.h>
#include <stdint.h>

#define BB   8
#define CIN  64
#define COUT 64
#define CG   16
#define HH   128
#define WW   128

// weight fragments fp16x2: [p(9)][kt(4)][ng(4)][lane(32)][j(4)]
__device__ uint32_t g_wfrag[9 * 4 * 4 * 32 * 4];

// smem layout (bytes)
#define SOFF_KERN 0                    // 8 non-center taps * 128 * 2B = 2048
#define SOFF_XH   2048                 // [dh(3)][col(130)] rows of 128B, swizzled
#define SMEM_TOTAL (2048 + 3 * 130 * 128)   // 51968

__device__ __forceinline__ uint32_t smem_u32(const void* p) {
    uint32_t a;
    asm("{ .reg .u64 t; cvta.to.shared.u64 t, %1; cvt.u32.u64 %0, t; }"
        : "=r"(a) : "l"(p));
    return a;
}
__device__ __forceinline__ void ldm_x4(uint32_t r[4], uint32_t addr) {
    asm volatile("ldmatrix.sync.aligned.m8n8.x4.shared.b16 {%0,%1,%2,%3}, [%4];"
                 : "=r"(r[0]), "=r"(r[1]), "=r"(r[2]), "=r"(r[3]) : "r"(addr));
}
__device__ __forceinline__ uint32_t hmul2(uint32_t a, uint32_t k) {
    uint32_t d;
    asm("mul.f16x2 %0, %1, %2;" : "=r"(d) : "r"(a), "r"(k));
    return d;
}
#define MMA_F16(d, a, b0, b1)                                                  \
    asm volatile("mma.sync.aligned.m16n8k16.row.col.f32.f16.f16.f32 "          \
                 "{%0,%1,%2,%3}, {%4,%5,%6,%7}, {%8,%9}, {%0,%1,%2,%3};"       \
                 : "+f"((d)[0]), "+f"((d)[1]), "+f"((d)[2]), "+f"((d)[3])      \
                 : "r"((a)[0]), "r"((a)[1]), "r"((a)[2]), "r"((a)[3]),         \
                   "r"(b0), "r"(b1))

// ---------------------------------------------------------------------------
// weight prep: mma B-fragment order, fp16 (unchanged — proven)
// ---------------------------------------------------------------------------
__global__ void weight_split(const float* __restrict__ weight) {
    int i = blockIdx.x * 256 + threadIdx.x;
    if (i >= 9 * 4 * 4 * 32 * 4) return;
    int p    = i >> 11;
    int kt   = (i >> 9) & 3;
    int ng   = (i >> 7) & 3;
    int lane = (i >> 2) & 31;
    int j    = i & 3;
    int o = (ng * 2 + (j >> 1)) * 8 + (lane >> 2);
    int c = kt * 16 + (lane & 3) * 2 + (j & 1) * 8;
    __half h0 = __float2half_rn(weight[((size_t)o * CIN + c) * 9 + p]);
    __half h1 = __float2half_rn(weight[((size_t)o * CIN + c + 1) * 9 + p]);
    g_wfrag[i] = ((uint32_t)__half_as_ushort(h1) << 16) | __half_as_ushort(h0);
}

// ---------------------------------------------------------------------------
// Main: one CTA = ONE output row, 256 threads, 4 CTAs/SM.
// X halo rows are 128B with 16B-block XOR swizzle (blk ^ (col&7)) — bank-safe
// without padding, fitting 4 CTAs under the 228KB smem ceiling.
// Overlapped prologue (gaussian || staging). Mainloop = proven R13/R16 form.
// ---------------------------------------------------------------------------
__global__ __launch_bounds__(256, 4)
void pac_mma(const float* __restrict__ x,
             const float* __restrict__ guide,
             const float* __restrict__ bias,
             float* __restrict__ out) {
    extern __shared__ __align__(16) char smem[];
    const uint32_t sb = smem_u32(smem);
    unsigned short* kern_s = (unsigned short*)(smem + SOFF_KERN); // [q][pix] half
    char*           xbase  = smem + SOFF_XH;

    const int tid   = threadIdx.x;
    const int lane  = tid & 31;
    const int wid   = tid >> 5;
    const int warpM = wid & 3;
    const int warpN = wid >> 2;
    const int h = blockIdx.x;
    const int b = blockIdx.y;

    if (tid < 128) {
        // ---- gaussian taps from global guide (L2-hot), 8 non-center taps ----
        const int pix = tid;
        const float* gb = guide + (size_t)b * CG * HH * WW;
        float gc[CG];
#pragma unroll
        for (int c = 0; c < CG; c++)
            gc[c] = __ldg(&gb[c * HH * WW + h * WW + pix]);
#pragma unroll
        for (int p = 0; p < 9; p++) {
            if (p == 4) continue;                    // center: kv == 1
            int gr = h - 1 + p / 3;
            int gw = pix - 1 + p % 3;
            float ss = 0.f;
            if (gr >= 0 && gr < HH && gw >= 0 && gw < WW) {
#pragma unroll
                for (int c = 0; c < CG; c++) {
                    float d = __ldg(&gb[c * HH * WW + gr * WW + gw]) - gc[c];
                    ss = fmaf(d, d, ss);
                }
            } else {
#pragma unroll
                for (int c = 0; c < CG; c++) ss = fmaf(gc[c], gc[c], ss);
            }
            float kv = __expf(-0.5f * ss);
            const int q = (p < 4) ? p : p - 1;
            kern_s[q * 128 + pix] = __half_as_ushort(__float2half_rn(kv));
        }
    } else {
        // ---- stage x halo fp16: rows 128B, 16B-block swizzle; STS.128 ----
        for (int i = tid - 128; i < 3120; i += 128) {   // 3 dh * 8 j * 130 col
            int col = i % 130;
            int q   = i / 130;
            int j   = q & 7;            // 16B channel block (8 channels)
            int dh  = q >> 3;
            int c0  = j * 8;
            int gr = h - 1 + dh, gc = col - 1;
            const bool ok = (gr >= 0) && (gr < HH) && (gc >= 0) && (gc < WW);
            const float* xp = x + ((size_t)(b * CIN + c0) * HH + gr) * WW + gc;
            __half hv[8];
#pragma unroll
            for (int k = 0; k < 8; k++) {
                float v = ok ? __ldg(xp + (size_t)k * (HH * WW)) : 0.f;
                hv[k] = __float2half_rn(v);
            }
            *(uint4*)(xbase + ((dh * 130 + col) << 7) +
                      (((j ^ (col & 7)) << 4))) = *(const uint4*)hv;
        }
    }
    __syncthreads();

    float acc[2][4][4];
#pragma unroll
    for (int i = 0; i < 2; i++)
#pragma unroll
        for (int j = 0; j < 4; j++)
#pragma unroll
            for (int k = 0; k < 4; k++) acc[i][j][k] = 0.f;

    const int pixb = warpM * 32;
    const int cb   = pixb + (lane & 15);     // halo-col base for this lane
    const int lh   = lane >> 4;              // 16B-block half select (0/1)
    const uint4* b_base = (const uint4*)g_wfrag + warpN * 64 + lane;
    const int pix0 = pixb + (lane >> 2);

    // ---- mainloop: 9 taps, barrier-free, kv folded into A ----
#pragma unroll
    for (int p = 0; p < 9; p++) {
        const int dh = p / 3, dw = p - dh * 3;
        const uint4* bt = b_base + (size_t)(p * 4) * 128;

        // per-mt row address + swizzle key (hoisted out of kt loop)
        uint32_t rowb[2];
        int c7[2];
#pragma unroll
        for (int mt = 0; mt < 2; mt++) {
            const int colrow = cb + dw + mt * 16;
            rowb[mt] = sb + SOFF_XH + (uint32_t)((dh * 130 + colrow) << 7);
            c7[mt]   = colrow & 7;
        }

        uint32_t kv2[2][2];
        if (p != 4) {                 // center tap: kv == 1 exactly, skip fold
            const int q = (p < 4) ? p : p - 1;
#pragma unroll
            for (int mt = 0; mt < 2; mt++) {
                uint32_t u0 = kern_s[q * 128 + pix0 + mt * 16];
                uint32_t u1 = kern_s[q * 128 + pix0 + mt * 16 + 8];
                kv2[mt][0] = (u0 << 16) | u0;
                kv2[mt][1] = (u1 << 16) | u1;
            }
        }

#pragma unroll
        for (int kt = 0; kt < 4; kt++) {
            uint4 b0 = __ldg(bt + (size_t)kt * 128);
            uint4 b1 = __ldg(bt + (size_t)kt * 128 + 32);
            const int jk = (kt << 1) | lh;
#pragma unroll
            for (int mt = 0; mt < 2; mt++) {
                uint32_t A[4];
                ldm_x4(A, rowb[mt] + (uint32_t)((jk ^ c7[mt]) << 4));
                if (p != 4) {
                    // row map: A[0],A[2] -> pixel g ; A[1],A[3] -> pixel g+8
                    A[0] = hmul2(A[0], kv2[mt][0]);
                    A[2] = hmul2(A[2], kv2[mt][0]);
                    A[1] = hmul2(A[1], kv2[mt][1]);
                    A[3] = hmul2(A[3], kv2[mt][1]);
                }
                MMA_F16(acc[mt][0], A, b0.x, b0.y);
                MMA_F16(acc[mt][1], A, b0.z, b0.w);
                MMA_F16(acc[mt][2], A, b1.x, b1.y);
                MMA_F16(acc[mt][3], A, b1.z, b1.w);
            }
        }
    }

    // ---- epilogue: bias (direct ldg) + relu ----
#pragma unroll
    for (int mt = 0; mt < 2; mt++) {
        const int pix = pix0 + mt * 16;
#pragma unroll
        for (int nt = 0; nt < 4; nt++) {
            int o = (warpN * 4 + nt) * 8 + (lane & 3) * 2;
            float b0 = __ldg(&bias[o]);
            float b1 = __ldg(&bias[o + 1]);
            float* op = out + (((size_t)b * COUT + o) * HH + h) * WW;
            op[pix]               = fmaxf(acc[mt][nt][0] + b0, 0.f);
            op[HH * WW + pix]     = fmaxf(acc[mt][nt][1] + b1, 0.f);
            op[pix + 8]           = fmaxf(acc[mt][nt][2] + b0, 0.f);
            op[HH * WW + pix + 8] = fmaxf(acc[mt][nt][3] + b1, 0.f);
        }
    }
}

// ---------------------------------------------------------------------------
extern "C" void kernel_launch(void* const* d_in, const int* in_sizes, int n_in,
                              void* d_out, int out_size) {
    const float* x      = (const float*)d_in[0];   // (8,64,128,128)
    const float* guide  = (const float*)d_in[1];   // (8,16,128,128)
    const float* weight = (const float*)d_in[2];   // (64,64,3,3)
    const float* bias   = (const float*)d_in[3];   // (64,)
    float* out = (float*)d_out;                    // (8,64,128,128)

    (void)in_sizes; (void)n_in; (void)out_size;

    cudaFuncSetAttribute(pac_mma, cudaFuncAttributeMaxDynamicSharedMemorySize,
                         SMEM_TOTAL);

    weight_split<<<(9 * 4 * 4 * 32 * 4 + 255) / 256, 256>>>(weight);

    dim3 grid(HH, BB);
    pac_mma<<<grid, 256, SMEM_TOTAL>>>(x, guide, bias, out);
}